// round 8
// baseline (speedup 1.0000x reference)
#include <cuda_runtime.h>
#include <cuda_bf16.h>
#include <stdint.h>

// Problem constants
#define N_G 8
#define M_C 512
#define D_C 64
#define BL  32768            // tokens per group
#define TPB 256              // threads per CTA = tokens per CTA
#define NTILES 64            // 512 codes / 8 per mma-n-tile

// ---------------- device scratch (no cudaMalloc allowed) ----------------
__device__ int    g_hist[N_G * M_C];
__device__ double g_loss;
__device__ __align__(128) unsigned short g_ebf[N_G * M_C * D_C]; // bf16 codebook, chunk-swizzled rows
__device__ float  g_e2[N_G * M_C];                               // exact sequential ||e||^2

// smem layout (bytes, dynamic)
#define SM_E    0        // 512 x 128B bf16 codebook       = 65536
#define SM_A    65536    // 256 x 128B bf16 tokens          = 32768
#define SM_E2   98304    // 512 f32                         = 2048
#define SM_X2   100352   // 256 f32                         = 1024
#define SM_SLOT 101376   // 256 rows x 12 shorts            = 6144
#define SM_RED  107520   // 8 f32
#define SM_TOT  107648

__device__ __forceinline__ uint32_t smem_u32(const void* p) {
    uint32_t a;
    asm("{ .reg .u64 t; cvta.to.shared.u64 t, %1; cvt.u32.u64 %0, t; }" : "=r"(a) : "l"(p));
    return a;
}

#define LDSM4(r0,r1,r2,r3,addr) \
    asm volatile("ldmatrix.sync.aligned.m8n8.x4.shared.b16 {%0,%1,%2,%3}, [%4];" \
        : "=r"(r0),"=r"(r1),"=r"(r2),"=r"(r3) : "r"(addr))
#define LDSM2(r0,r1,addr) \
    asm volatile("ldmatrix.sync.aligned.m8n8.x2.shared.b16 {%0,%1}, [%2];" \
        : "=r"(r0),"=r"(r1) : "r"(addr))
#define MMA16816(c0,c1,c2,c3,a0,a1,a2,a3,b0,b1) \
    asm volatile("mma.sync.aligned.m16n8k16.row.col.f32.bf16.bf16.f32 " \
        "{%0,%1,%2,%3}, {%4,%5,%6,%7}, {%8,%9}, {%0,%1,%2,%3};" \
        : "+f"(c0),"+f"(c1),"+f"(c2),"+f"(c3) \
        : "r"(a0),"r"(a1),"r"(a2),"r"(a3),"r"(b0),"r"(b1))

// candidate tracking: provable window, 3-deep list, compaction, overflow flag
#define TRK(R, SPV, MV) { float sp_ = (SPV); \
    if (sp_ <= lmin##R + W##R) { \
        if (sp_ < lmin##R) lmin##R = sp_; \
        if (cnt##R == 3) { \
            float t_ = lmin##R + W##R; int k_ = 0; \
            float nv0 = 0.f, nv1 = 0.f, nv2 = 0.f; int ni0 = 0, ni1 = 0, ni2 = 0; \
            if (cv##R##0 <= t_) { nv0 = cv##R##0; ni0 = ci##R##0; k_ = 1; } \
            if (cv##R##1 <= t_) { if (k_ == 0) { nv0 = cv##R##1; ni0 = ci##R##1; } \
                                  else         { nv1 = cv##R##1; ni1 = ci##R##1; } k_++; } \
            if (cv##R##2 <= t_) { if (k_ == 0) { nv0 = cv##R##2; ni0 = ci##R##2; } \
                                  else if (k_ == 1) { nv1 = cv##R##2; ni1 = ci##R##2; } \
                                  else { nv2 = cv##R##2; ni2 = ci##R##2; } k_++; } \
            cv##R##0 = nv0; ci##R##0 = ni0; cv##R##1 = nv1; ci##R##1 = ni1; \
            cv##R##2 = nv2; ci##R##2 = ni2; cnt##R = k_; \
        } \
        if      (cnt##R == 0) { cv##R##0 = sp_; ci##R##0 = (MV); cnt##R = 1; } \
        else if (cnt##R == 1) { cv##R##1 = sp_; ci##R##1 = (MV); cnt##R = 2; } \
        else if (cnt##R == 2) { cv##R##2 = sp_; ci##R##2 = (MV); cnt##R = 3; } \
        else ovf##R = 1; \
    } }

#define FLUSH(R, GROW) { \
    float gm_ = fminf(lmin##R, __shfl_xor_sync(0xffffffffu, lmin##R, 1)); \
    gm_ = fminf(gm_, __shfl_xor_sync(0xffffffffu, gm_, 2)); \
    float t_ = gm_ + W##R; \
    int base_ = (GROW) * 12 + (lane & 3) * 3; int k_ = 0; \
    if (ovf##R) { slots[base_] = -2; } \
    else { \
        if (cnt##R > 0 && cv##R##0 <= t_) slots[base_ + k_++] = (short)ci##R##0; \
        if (cnt##R > 1 && cv##R##1 <= t_) slots[base_ + k_++] = (short)ci##R##1; \
        if (cnt##R > 2 && cv##R##2 <= t_) slots[base_ + k_++] = (short)ci##R##2; \
    } }

// ---------------- kernels ----------------
__global__ void vq_zero() {
    int i = blockIdx.x * blockDim.x + threadIdx.x;
    if (i < N_G * M_C) g_hist[i] = 0;
    if (i == 0) g_loss = 0.0;
}

// One thread per code: exact-sequential e2; bf16 row stored with 16B-chunk XOR swizzle.
__global__ void vq_prep(const float* __restrict__ emb) {
    int gm = blockIdx.x * blockDim.x + threadIdx.x;
    if (gm >= N_G * M_C) return;
    const float* ep = emb + (size_t)gm * D_C;
    float s = 0.f;
    unsigned short row[D_C];
#pragma unroll
    for (int d = 0; d < D_C; d++) {
        float v = ep[d];
        s = __fadd_rn(s, __fmul_rn(v, v));
        row[d] = __bfloat16_as_ushort(__float2bfloat16(v));
    }
    g_e2[gm] = s;
    uint4* base = (uint4*)(g_ebf + (size_t)gm * D_C);
#pragma unroll
    for (int c = 0; c < 8; c++) {
        uint4 w;
        w.x = (uint32_t)row[8*c+0] | ((uint32_t)row[8*c+1] << 16);
        w.y = (uint32_t)row[8*c+2] | ((uint32_t)row[8*c+3] << 16);
        w.z = (uint32_t)row[8*c+4] | ((uint32_t)row[8*c+5] << 16);
        w.w = (uint32_t)row[8*c+6] | ((uint32_t)row[8*c+7] << 16);
        base[c ^ (gm & 7)] = w;
    }
}

__global__ __launch_bounds__(TPB)
void vq_main(const float* __restrict__ x, const float* __restrict__ emb,
             float* __restrict__ out)
{
    extern __shared__ char sm[];
    const uint32_t smb = smem_u32(sm);
    const int tid  = threadIdx.x;
    const int lane = tid & 31;
    const int w    = tid >> 5;                 // warp 0..7
    const int n    = blockIdx.y;
    const int t    = blockIdx.x * TPB + tid;   // token id in [0, BL)
    const int b    = t >> 10, l = t & 1023;

    float* e2s = (float*)(sm + SM_E2);
    float* x2s = (float*)(sm + SM_X2);
    short* slots = (short*)(sm + SM_SLOT);

    // ---- phase 0: token load, exact x2, bf16 row -> A smem (swizzled)
    const float* xbase = x + (size_t)(b * 512 + n * 64) * 1024 + l;
    float xr[D_C];
#pragma unroll
    for (int d = 0; d < D_C; d++) xr[d] = xbase[(size_t)d * 1024];
    float x2 = 0.f;
#pragma unroll
    for (int d = 0; d < D_C; d++) x2 = __fadd_rn(x2, __fmul_rn(xr[d], xr[d]));
    x2s[tid] = x2;
    {
        char* abase = sm + SM_A + (size_t)tid * 128;
#pragma unroll
        for (int c = 0; c < 8; c++) {
            uint4 wv;
            uint32_t p[4];
#pragma unroll
            for (int q = 0; q < 4; q++) {
                __nv_bfloat16 h0 = __float2bfloat16(xr[8*c + 2*q]);
                __nv_bfloat16 h1 = __float2bfloat16(xr[8*c + 2*q + 1]);
                p[q] = (uint32_t)__bfloat16_as_ushort(h0) | ((uint32_t)__bfloat16_as_ushort(h1) << 16);
            }
            wv.x = p[0]; wv.y = p[1]; wv.z = p[2]; wv.w = p[3];
            *(uint4*)(abase + ((c ^ (tid & 7)) << 4)) = wv;
        }
    }
    // ---- phase 1: codebook bf16 (pre-swizzled) + e2 -> smem; slot init
    {
        const uint4* src = (const uint4*)(g_ebf + (size_t)n * M_C * D_C);
        uint4* dst = (uint4*)(sm + SM_E);
#pragma unroll
        for (int i = 0; i < 16; i++) dst[tid + i * TPB] = src[tid + i * TPB];
        const float* s2 = g_e2 + n * M_C;
        e2s[tid] = s2[tid]; e2s[tid + 256] = s2[tid + 256];
        int* si = (int*)slots;
#pragma unroll
        for (int i = 0; i < 6; i++) si[tid + i * TPB] = -1;   // two -1 shorts
    }
    __syncthreads();

    // ---- phase 2: fragment-domain scan. warp w owns token rows RB..RB+31
    const int RB = w * 32;

    // A fragments: 2 m-tiles x 4 k-steps x 4 regs
    uint32_t afr[2][4][4];
#pragma unroll
    for (int mt = 0; mt < 2; mt++)
#pragma unroll
        for (int ks = 0; ks < 4; ks++) {
            uint32_t row = RB + mt * 16 + (lane & 15);
            uint32_t chunk = 2 * ks + (lane >> 4);
            uint32_t addr = smb + SM_A + row * 128 + ((chunk ^ (row & 7)) << 4);
            LDSM4(afr[mt][ks][0], afr[mt][ks][1], afr[mt][ks][2], afr[mt][ks][3], addr);
        }

    // B ldmatrix base addresses (lane-fixed swizzle; +1024B per n-tile)
    uint32_t rowl = lane & 7;
    uint32_t par  = (lane >> 3) & 1;
    uint32_t bb   = smb + SM_E + rowl * 128;
    uint32_t ba[4];
#pragma unroll
    for (int ks = 0; ks < 4; ks++) ba[ks] = bb + (((2u*ks + par) ^ rowl) << 4);

    // per-row windows from token norms (rows this thread's fragments cover)
    float W0, W1, W2, W3;
    {
        int r0 = RB + (lane >> 2);
        W0 = 4.f * (__fsqrt_rn(x2s[r0     ]) * 6.15e-5f + 1e-6f) + 5e-5f;
        W1 = 4.f * (__fsqrt_rn(x2s[r0 +  8]) * 6.15e-5f + 1e-6f) + 5e-5f;
        W2 = 4.f * (__fsqrt_rn(x2s[r0 + 16]) * 6.15e-5f + 1e-6f) + 5e-5f;
        W3 = 4.f * (__fsqrt_rn(x2s[r0 + 24]) * 6.15e-5f + 1e-6f) + 5e-5f;
    }
    float lmin0 = 3.4e38f, lmin1 = 3.4e38f, lmin2 = 3.4e38f, lmin3 = 3.4e38f;
    float cv00, cv01, cv02, cv10, cv11, cv12, cv20, cv21, cv22, cv30, cv31, cv32;
    int   ci00, ci01, ci02, ci10, ci11, ci12, ci20, ci21, ci22, ci30, ci31, ci32;
    int   cnt0 = 0, cnt1 = 0, cnt2 = 0, cnt3 = 0;
    int   ovf0 = 0, ovf1 = 0, ovf2 = 0, ovf3 = 0;
    cv00=cv01=cv02=cv10=cv11=cv12=cv20=cv21=cv22=cv30=cv31=cv32 = 0.f;
    ci00=ci01=ci02=ci10=ci11=ci12=ci20=ci21=ci22=ci30=ci31=ci32 = 0;

#pragma unroll 1
    for (int j = 0; j < NTILES; j++) {
        uint32_t b0[4], b1[4];
#pragma unroll
        for (int ks = 0; ks < 4; ks++) LDSM2(b0[ks], b1[ks], ba[ks] + j * 1024u);

        float c00 = 0.f, c01 = 0.f, c02 = 0.f, c03 = 0.f;
        float c10 = 0.f, c11 = 0.f, c12 = 0.f, c13 = 0.f;
#pragma unroll
        for (int ks = 0; ks < 4; ks++) {
            MMA16816(c00, c01, c02, c03,
                     afr[0][ks][0], afr[0][ks][1], afr[0][ks][2], afr[0][ks][3],
                     b0[ks], b1[ks]);
            MMA16816(c10, c11, c12, c13,
                     afr[1][ks][0], afr[1][ks][1], afr[1][ks][2], afr[1][ks][3],
                     b0[ks], b1[ks]);
        }
        int n0 = j * 8 + (lane & 3) * 2;
        float e20 = e2s[n0], e21 = e2s[n0 + 1];
        TRK(0, __fmaf_rn(-2.f, c00, e20), n0);
        TRK(0, __fmaf_rn(-2.f, c01, e21), n0 + 1);
        TRK(1, __fmaf_rn(-2.f, c02, e20), n0);
        TRK(1, __fmaf_rn(-2.f, c03, e21), n0 + 1);
        TRK(2, __fmaf_rn(-2.f, c10, e20), n0);
        TRK(2, __fmaf_rn(-2.f, c11, e21), n0 + 1);
        TRK(3, __fmaf_rn(-2.f, c12, e20), n0);
        TRK(3, __fmaf_rn(-2.f, c13, e21), n0 + 1);
    }

    {
        int r0 = RB + (lane >> 2);
        FLUSH(0, r0);
        FLUSH(1, r0 + 8);
        FLUSH(2, r0 + 16);
        FLUSH(3, r0 + 24);
    }
    __syncthreads();

    // ---- phase 3: token-domain exact rescore (reference rounding pipeline)
    const float* embn = emb + (size_t)n * M_C * D_C;
    float bestd = 3.4e38f; int bestm = M_C;   // bestm sentinel > any index
    bool full = false;
    int cand[12]; int nc = 0;
#pragma unroll
    for (int s = 0; s < 12; s++) {
        short m = slots[tid * 12 + s];
        if (m == -2) full = true;
        else if (m >= 0) cand[nc++] = m;
    }
    if (full) {
        for (int m = 0; m < M_C; m++) {
            const float* ep = embn + (size_t)m * D_C;
            float a = 0.f;
#pragma unroll
            for (int d = 0; d < D_C; d++) a = __fmaf_rn(xr[d], ep[d], a);
            float d2 = __fadd_rn(__fsub_rn(x2, __fmul_rn(2.f, a)), e2s[m]);
            if (d2 < bestd) { bestd = d2; bestm = m; }
        }
    } else {
        for (int i = 0; i < nc; i++) {
            int m = cand[i];
            const float* ep = embn + (size_t)m * D_C;
            float a = 0.f;
#pragma unroll
            for (int d = 0; d < D_C; d++) a = __fmaf_rn(xr[d], ep[d], a);
            float d2 = __fadd_rn(__fsub_rn(x2, __fmul_rn(2.f, a)), e2s[m]);
            if (d2 < bestd || (d2 == bestd && m < bestm)) { bestd = d2; bestm = m; }
        }
    }

    // ---- phase 4: output, histogram, loss
    const float* eb = embn + (size_t)bestm * D_C;
    float* obase = out + (size_t)(b * 512 + n * 64) * 1024 + l;
    float lsum = 0.f;
#pragma unroll
    for (int d = 0; d < D_C; d++) {
        float q = eb[d], xv = xr[d];
        obase[(size_t)d * 1024] = __fadd_rn(xv, __fsub_rn(q, xv));
        float df = xv - q;
        lsum += df * df;
    }
    atomicAdd(&g_hist[n * M_C + bestm], 1);

    float* red = (float*)(sm + SM_RED);
#pragma unroll
    for (int o = 16; o > 0; o >>= 1) lsum += __shfl_down_sync(0xffffffffu, lsum, o);
    if (lane == 0) red[w] = lsum;
    __syncthreads();
    if (tid == 0) {
        float s = 0.f;
#pragma unroll
        for (int i = 0; i < 8; i++) s += red[i];
        atomicAdd(&g_loss, (double)s);
    }
}

__global__ void vq_final(float* __restrict__ out, int loss_idx)
{
    __shared__ float pn[N_G];
    if (threadIdx.x < N_G) pn[threadIdx.x] = 0.f;
    __syncthreads();
    for (int i = threadIdx.x; i < N_G * M_C; i += blockDim.x) {
        float p = (float)g_hist[i] / (float)BL;
        atomicAdd(&pn[i / M_C], p * logf(p + 1e-10f));
    }
    __syncthreads();
    if (threadIdx.x == 0) {
        float perp = 0.f;
#pragma unroll
        for (int nn = 0; nn < N_G; nn++) perp += expf(-pn[nn]);
        double mean = g_loss / (double)((size_t)N_G * BL * D_C);
        out[loss_idx] = (float)(0.25 * mean);
        out[loss_idx + 1] = perp;
    }
}

extern "C" void kernel_launch(void* const* d_in, const int* in_sizes, int n_in,
                              void* d_out, int out_size)
{
    const float* x   = (const float*)d_in[0];   // [32, 512, 1024] f32
    const float* emb = (const float*)d_in[1];   // [8, 512, 64]   f32
    float* out = (float*)d_out;

    cudaFuncSetAttribute(vq_main, cudaFuncAttributeMaxDynamicSharedMemorySize, SM_TOT);

    vq_prep<<<(N_G * M_C + 127) / 128, 128>>>(emb);
    vq_zero<<<(N_G * M_C + 255) / 256, 256>>>();

    dim3 grid(BL / TPB, N_G);
    vq_main<<<grid, TPB, SM_TOT>>>(x, emb, out);

    vq_final<<<1, 512>>>(out, out_size - 2);
}

// round 9
// speedup vs baseline: 1.5930x; 1.5930x over previous
#include <cuda_runtime.h>
#include <stdint.h>

// Problem constants
#define N_G 8
#define M_C 512
#define D_C 64
#define BL  32768           // tokens per group
#define TPB 128
#define CAP 10              // candidate list capacity

// ---------------- device scratch (no cudaMalloc allowed) ----------------
__device__ int    g_hist[N_G * M_C];
__device__ double g_loss;
__device__ __align__(16) int    g_qe[N_G * M_C * 16];  // int8-packed codebook (16 words/code)
__device__ __align__(8)  float2 g_sc[N_G * M_C];       // {se scale, exact-seq e2}

// ---------------- kernels ----------------
__global__ void vq_zero() {
    int i = blockIdx.x * blockDim.x + threadIdx.x;
    if (i < N_G * M_C) g_hist[i] = 0;
    if (i == 0) g_loss = 0.0;
}

// One thread per code: exact-sequential e2 (reference order), int8 quantization.
__global__ void vq_prep(const float* __restrict__ emb) {
    int gm = blockIdx.x * blockDim.x + threadIdx.x;
    if (gm >= N_G * M_C) return;
    const float* ep = emb + (size_t)gm * D_C;
    float e[D_C];
    float s = 0.f, mx = 1e-30f;
#pragma unroll
    for (int d = 0; d < D_C; d++) {
        e[d] = ep[d];
        s = __fadd_rn(s, __fmul_rn(e[d], e[d]));
        mx = fmaxf(mx, fabsf(e[d]));
    }
    float se  = mx / 127.f;
    float inv = 127.f / mx;
    int* dst = g_qe + gm * 16;
#pragma unroll
    for (int w = 0; w < 16; w++) {
        int q0 = __float2int_rn(e[4 * w + 0] * inv);
        int q1 = __float2int_rn(e[4 * w + 1] * inv);
        int q2 = __float2int_rn(e[4 * w + 2] * inv);
        int q3 = __float2int_rn(e[4 * w + 3] * inv);
        unsigned pk = (unsigned)(q0 & 0xFF) | ((unsigned)(q1 & 0xFF) << 8)
                    | ((unsigned)(q2 & 0xFF) << 16) | ((unsigned)(q3 & 0xFF) << 24);
        dst[w] = (int)pk;
    }
    g_sc[gm] = make_float2(se, s);
}

// candidate insert: provable window, running min, compaction, overflow flag
#define INS(MM, SPV) { float sp_ = (SPV);                                        \
    if (sp_ <= run + W) {                                                        \
        if (sp_ < run) run = sp_;                                                \
        if (cnt == CAP) { int k_ = 0;                                            \
            for (int z = 0; z < CAP; z++)                                        \
                if (cv[z] <= run + W) { cv[k_] = cv[z]; ci[k_] = ci[z]; k_++; }  \
            cnt = k_; }                                                          \
        if (cnt < CAP) { cv[cnt] = sp_; ci[cnt] = (MM); cnt++; }                 \
        else ovf = true; } }

__global__ __launch_bounds__(TPB)
void vq_main(const float* __restrict__ x, const float* __restrict__ emb,
             float* __restrict__ out)
{
    __shared__ int    sqe[M_C * 16];   // 32 KB int8 codebook (packed words)
    __shared__ float2 ssc[M_C];        // 4 KB {se, e2}
    __shared__ float  red[TPB / 32];

    const int tid = threadIdx.x;
    const int n = blockIdx.y;
    const int t = blockIdx.x * TPB + tid;      // token id in [0, BL)
    const int b = t >> 10, l = t & 1023;

    // ---- phase 0: token load (coalesced), exact-seq x2, |x| stats, int8 quantize
    const float* xbase = x + (size_t)(b * 512 + n * 64) * 1024 + l;
    float xr[D_C];
#pragma unroll
    for (int d = 0; d < D_C; d++) xr[d] = xbase[(size_t)d * 1024];

    float x2 = 0.f;
#pragma unroll
    for (int d = 0; d < D_C; d++) x2 = __fadd_rn(x2, __fmul_rn(xr[d], xr[d]));

    float sa = 0.f, mx = 1e-30f;
#pragma unroll
    for (int d = 0; d < D_C; d++) { float a = fabsf(xr[d]); sa += a; mx = fmaxf(mx, a); }
    const float sx  = mx / 127.f;
    const float inv = 127.f / mx;

    int qx[16];
#pragma unroll
    for (int w = 0; w < 16; w++) {
        int q0 = __float2int_rn(xr[4 * w + 0] * inv);
        int q1 = __float2int_rn(xr[4 * w + 1] * inv);
        int q2 = __float2int_rn(xr[4 * w + 2] * inv);
        int q3 = __float2int_rn(xr[4 * w + 3] * inv);
        unsigned pk = (unsigned)(q0 & 0xFF) | ((unsigned)(q1 & 0xFF) << 8)
                    | ((unsigned)(q2 & 0xFF) << 16) | ((unsigned)(q3 & 0xFF) << 24);
        qx[w] = (int)pk;
    }

    // ---- phase 1: cooperative codebook stage (whole group fits in smem)
    {
        const uint4* src = (const uint4*)(g_qe + (size_t)n * M_C * 16);
        uint4* dst = (uint4*)sqe;
#pragma unroll
        for (int i = 0; i < 16; i++) dst[tid + i * TPB] = src[tid + i * TPB];
        const float2* s2 = g_sc + n * M_C;
#pragma unroll
        for (int i = 0; i < 4; i++) ssc[tid + i * TPB] = s2[tid + i * TPB];
    }
    __syncthreads();

    // rigorous screen-error bound:
    //   err <= 0.5*sx*Sum|e| + (Sum|x| + 64*0.5*sx)*0.5*se,  Sum|e|<=0.125, se<=1.55e-5
    const float E = 0.5f * sx * 0.125f + (sa + 32.f * sx) * (0.5f * 1.55e-5f);
    const float W = 4.f * E + 5e-5f;     // two codes compared + ref-grid/fp slack
    const float c = -2.f * sx;

    float run = 3.4e38f;
    float cv[CAP]; int ci[CAP];
    int cnt = 0; bool ovf = false;

    // ---- phase 2: dp4a screen, 2 codes per iteration (dual independent chains)
#pragma unroll 2
    for (int m = 0; m < M_C; m += 2) {
        const int4* qa = (const int4*)(sqe + m * 16);
        int4 A0 = qa[0], A1 = qa[1], A2 = qa[2], A3 = qa[3];
        int4 B0 = qa[4], B1 = qa[5], B2 = qa[6], B3 = qa[7];
        int i0 = 0, i1 = 0;
        i0 = __dp4a(qx[0],  A0.x, i0);  i1 = __dp4a(qx[0],  B0.x, i1);
        i0 = __dp4a(qx[1],  A0.y, i0);  i1 = __dp4a(qx[1],  B0.y, i1);
        i0 = __dp4a(qx[2],  A0.z, i0);  i1 = __dp4a(qx[2],  B0.z, i1);
        i0 = __dp4a(qx[3],  A0.w, i0);  i1 = __dp4a(qx[3],  B0.w, i1);
        i0 = __dp4a(qx[4],  A1.x, i0);  i1 = __dp4a(qx[4],  B1.x, i1);
        i0 = __dp4a(qx[5],  A1.y, i0);  i1 = __dp4a(qx[5],  B1.y, i1);
        i0 = __dp4a(qx[6],  A1.z, i0);  i1 = __dp4a(qx[6],  B1.z, i1);
        i0 = __dp4a(qx[7],  A1.w, i0);  i1 = __dp4a(qx[7],  B1.w, i1);
        i0 = __dp4a(qx[8],  A2.x, i0);  i1 = __dp4a(qx[8],  B2.x, i1);
        i0 = __dp4a(qx[9],  A2.y, i0);  i1 = __dp4a(qx[9],  B2.y, i1);
        i0 = __dp4a(qx[10], A2.z, i0);  i1 = __dp4a(qx[10], B2.z, i1);
        i0 = __dp4a(qx[11], A2.w, i0);  i1 = __dp4a(qx[11], B2.w, i1);
        i0 = __dp4a(qx[12], A3.x, i0);  i1 = __dp4a(qx[12], B3.x, i1);
        i0 = __dp4a(qx[13], A3.y, i0);  i1 = __dp4a(qx[13], B3.y, i1);
        i0 = __dp4a(qx[14], A3.z, i0);  i1 = __dp4a(qx[14], B3.z, i1);
        i0 = __dp4a(qx[15], A3.w, i0);  i1 = __dp4a(qx[15], B3.w, i1);

        float2 s0 = ssc[m], s1 = ssc[m + 1];
        // idot < 2^24 so I2F is exact; sp = e2 - 2*sx*se*idot
        float sp0 = __fmaf_rn(c, __int2float_rn(i0) * s0.x, s0.y);
        float sp1 = __fmaf_rn(c, __int2float_rn(i1) * s1.x, s1.y);
        INS(m,     sp0);
        INS(m + 1, sp1);
    }

    // final prune against final running min
    if (!ovf) {
        int k2 = 0;
        for (int z = 0; z < cnt; z++)
            if (cv[z] <= run + W) { cv[k2] = cv[z]; ci[k2] = ci[z]; k2++; }
        cnt = k2;
    }

    // ---- phase 3: exact rescore (bit-exact reference rounding pipeline)
    const float* embn = emb + (size_t)n * M_C * D_C;
    float bestd = 3.4e38f; int bestm = M_C;
    if (ovf) {                                   // deterministic fallback (≈ never)
        for (int m = 0; m < M_C; m++) {
            const float* ep = embn + (size_t)m * D_C;
            float a = 0.f;
#pragma unroll
            for (int d = 0; d < D_C; d++) a = __fmaf_rn(xr[d], ep[d], a);
            float d2 = __fadd_rn(__fsub_rn(x2, __fmul_rn(2.f, a)), ssc[m].y);
            if (d2 < bestd) { bestd = d2; bestm = m; }
        }
    } else {
        for (int i = 0; i < cnt; i++) {
            int m = ci[i];
            const float* ep = embn + (size_t)m * D_C;
            float a = 0.f;
#pragma unroll
            for (int d = 0; d < D_C; d++) a = __fmaf_rn(xr[d], ep[d], a);
            float d2 = __fadd_rn(__fsub_rn(x2, __fmul_rn(2.f, a)), ssc[m].y);
            if (d2 < bestd || (d2 == bestd && m < bestm)) { bestd = d2; bestm = m; }
        }
    }

    // ---- phase 4: output (straight-through), histogram, loss
    const float* eb = embn + (size_t)bestm * D_C;
    float* obase = out + (size_t)(b * 512 + n * 64) * 1024 + l;
    float lsum = 0.f;
#pragma unroll
    for (int d = 0; d < D_C; d++) {
        float q = eb[d], xv = xr[d];
        obase[(size_t)d * 1024] = __fadd_rn(xv, __fsub_rn(q, xv));
        float df = xv - q;
        lsum += df * df;
    }
    atomicAdd(&g_hist[n * M_C + bestm], 1);

#pragma unroll
    for (int o = 16; o > 0; o >>= 1) lsum += __shfl_down_sync(0xffffffffu, lsum, o);
    if ((tid & 31) == 0) red[tid >> 5] = lsum;
    __syncthreads();
    if (tid == 0) {
        float s = red[0] + red[1] + red[2] + red[3];
        atomicAdd(&g_loss, (double)s);
    }
}

// warp-per-group scalar finalize (no smem atomics, no serial logf bottleneck)
__global__ void vq_final(float* __restrict__ out, int loss_idx)
{
    __shared__ float pg[N_G];
    int w = threadIdx.x >> 5, lane = threadIdx.x & 31;
    if (w < N_G) {
        float s = 0.f;
        for (int i = lane; i < M_C; i += 32) {
            float p = (float)g_hist[w * M_C + i] / (float)BL;
            s += p * logf(p + 1e-10f);
        }
#pragma unroll
        for (int o = 16; o > 0; o >>= 1) s += __shfl_down_sync(0xffffffffu, s, o);
        if (lane == 0) pg[w] = s;
    }
    __syncthreads();
    if (threadIdx.x == 0) {
        float perp = 0.f;
#pragma unroll
        for (int g = 0; g < N_G; g++) perp += expf(-pg[g]);
        double mean = g_loss / (double)((size_t)N_G * BL * D_C);
        out[loss_idx]     = (float)(0.25 * mean);
        out[loss_idx + 1] = perp;
    }
}

extern "C" void kernel_launch(void* const* d_in, const int* in_sizes, int n_in,
                              void* d_out, int out_size)
{
    const float* x   = (const float*)d_in[0];   // [32, 512, 1024] f32
    const float* emb = (const float*)d_in[1];   // [8, 512, 64]   f32
    float* out = (float*)d_out;

    vq_prep<<<(N_G * M_C + 127) / 128, 128>>>(emb);
    vq_zero<<<(N_G * M_C + 255) / 256, 256>>>();

    dim3 grid(BL / TPB, N_G);
    vq_main<<<grid, TPB>>>(x, emb, out);

    vq_final<<<1, 256>>>(out, out_size - 2);
}

// round 13
// speedup vs baseline: 4.5633x; 2.8645x over previous
#include <cuda_runtime.h>
#include <stdint.h>

// Problem constants
#define N_G 8
#define M_C 512
#define D_C 64
#define BL  32768           // tokens per group
#define TPB 128
#define NPAIR 256           // code pairs per group

typedef unsigned long long u64;

// ---------------- device scratch (no cudaMalloc allowed) ----------------
__device__ int    g_hist[N_G * M_C];
__device__ double g_loss;
__device__ __align__(16) ulonglong2 g_ep[N_G * NPAIR * 32]; // pair-interleaved fp32 codebook
__device__ float  g_e2[N_G * M_C];                          // exact-sequential ||e||^2

__device__ __forceinline__ u64 pk2(float lo, float hi) {
    u64 r; asm("mov.b64 %0, {%1, %2};" : "=l"(r) : "f"(lo), "f"(hi)); return r;
}
__device__ __forceinline__ float2 upk2(u64 v) {
    float2 f; asm("mov.b64 {%0, %1}, %2;" : "=f"(f.x), "=f"(f.y) : "l"(v)); return f;
}
// packed dual fp32 FMA: each component is an independent IEEE fp32 fma.rn
__device__ __forceinline__ u64 ffma2(u64 a, u64 b, u64 c) {
    u64 d; asm("fma.rn.f32x2 %0, %1, %2, %3;" : "=l"(d) : "l"(a), "l"(b), "l"(c)); return d;
}

// ---------------- prep: zero scratch, exact e2, pair-interleave codebook ----------------
__global__ void vq_prep(const float* __restrict__ emb) {
    int gp = blockIdx.x * blockDim.x + threadIdx.x;   // 0..2047 (pair index)
    if (gp >= N_G * NPAIR) return;
    g_hist[2 * gp] = 0; g_hist[2 * gp + 1] = 0;
    if (gp == 0) g_loss = 0.0;

    const float* ea = emb + (size_t)(2 * gp) * D_C;
    const float* eb = ea + D_C;
    float A[D_C], B[D_C];
    float sa = 0.f, sb = 0.f;
#pragma unroll
    for (int d = 0; d < D_C; d++) {
        A[d] = ea[d]; sa = __fadd_rn(sa, __fmul_rn(A[d], A[d]));   // reference order
        B[d] = eb[d]; sb = __fadd_rn(sb, __fmul_rn(B[d], B[d]));
    }
    g_e2[2 * gp] = sa; g_e2[2 * gp + 1] = sb;

    ulonglong2* dst = g_ep + (size_t)gp * 32;
#pragma unroll
    for (int dq = 0; dq < 32; dq++) {
        ulonglong2 v;
        v.x = pk2(A[2 * dq],     B[2 * dq]);       // (e_m[d],   e_m+1[d])
        v.y = pk2(A[2 * dq + 1], B[2 * dq + 1]);   // (e_m[d+1], e_m+1[d+1])
        dst[dq] = v;
    }
}

// one FFMA2 chain step macro: advances chain 'a' over two d for one code pair
#define STEP(a, v) { a = ffma2(xx[2 * dq], (v).x, a); a = ffma2(xx[2 * dq + 1], (v).y, a); }

// compare one code's exact d2 against running best (strict <, ascending m = first-tie)
#define CMP(MM, DOT) { \
    float d2_ = __fadd_rn(__fsub_rn(x2, __fmul_rn(2.0f, (DOT))), se2[MM]); \
    if (d2_ < best) { best = d2_; bestm = (MM); } }

__global__ __launch_bounds__(TPB)
void vq_main(const float* __restrict__ x, const float* __restrict__ emb,
             float* __restrict__ out)
{
    __shared__ ulonglong2 sE[64 * 32];   // 32 KB: 64 pairs (128 codes) per chunk
    __shared__ float      se2[M_C];      // 2 KB
    __shared__ float      red[TPB / 32];

    const int tid = threadIdx.x;
    const int n = blockIdx.y;
    const int t = blockIdx.x * TPB + tid;       // token id in [0, BL)
    const int b = t >> 10, l = t & 1023;

    // ---- phase 0: stream x once: exact-seq x2 + duplicated-pack xx (no xr kept)
    const float* xbase = x + (size_t)(b * 512 + n * 64) * 1024 + l;
    float x2 = 0.f;
    u64 xx[D_C];
#pragma unroll
    for (int d = 0; d < D_C; d++) {
        float v = xbase[(size_t)d * 1024];
        x2 = __fadd_rn(x2, __fmul_rn(v, v));
        xx[d] = pk2(v, v);
    }

    // e2 for the whole group
    {
        const float* s2 = g_e2 + n * M_C;
#pragma unroll
        for (int i = 0; i < M_C / TPB; i++) se2[tid + i * TPB] = s2[tid + i * TPB];
    }

    float best = 3.402823466e38f;
    int   bestm = 0;

    // ---- exact scan: 4 chunks of 128 codes (64 pairs); 4 concurrent pair-chains
    for (int c = 0; c < 4; c++) {
        __syncthreads();
        const ulonglong2* src = g_ep + ((size_t)n * NPAIR + c * 64) * 32;
#pragma unroll
        for (int i = 0; i < 16; i++) sE[tid + i * TPB] = src[tid + i * TPB];
        __syncthreads();

#pragma unroll 1
        for (int p = 0; p < 64; p += 4) {
            u64 a0 = 0ull, a1 = 0ull, a2 = 0ull, a3 = 0ull;   // (+0.f, +0.f)
            const ulonglong2* e0 = sE + (p + 0) * 32;
            const ulonglong2* e1 = sE + (p + 1) * 32;
            const ulonglong2* e2p = sE + (p + 2) * 32;
            const ulonglong2* e3 = sE + (p + 3) * 32;
#pragma unroll
            for (int dq = 0; dq < 32; dq++) {
                ulonglong2 v0 = e0[dq], v1 = e1[dq], v2 = e2p[dq], v3 = e3[dq];
                STEP(a0, v0); STEP(a1, v1); STEP(a2, v2); STEP(a3, v3);
            }
            const int m0 = 2 * (c * 64 + p);    // ascending global code index
            float2 f0 = upk2(a0), f1 = upk2(a1), f2 = upk2(a2), f3 = upk2(a3);
            CMP(m0 + 0, f0.x); CMP(m0 + 1, f0.y);
            CMP(m0 + 2, f1.x); CMP(m0 + 3, f1.y);
            CMP(m0 + 4, f2.x); CMP(m0 + 5, f2.y);
            CMP(m0 + 6, f3.x); CMP(m0 + 7, f3.y);
        }
    }

    // ---- phase 4: reload exact x (L2-warm), emit output, histogram, loss
    const float* eb = emb + ((size_t)n * M_C + bestm) * D_C;
    float* obase = out + (size_t)(b * 512 + n * 64) * 1024 + l;
    float lsum = 0.f;
#pragma unroll
    for (int d = 0; d < D_C; d++) {
        float xv = xbase[(size_t)d * 1024];
        float q  = eb[d];
        obase[(size_t)d * 1024] = __fadd_rn(xv, __fsub_rn(q, xv));
        float df = xv - q;
        lsum += df * df;
    }
    atomicAdd(&g_hist[n * M_C + bestm], 1);

#pragma unroll
    for (int o = 16; o > 0; o >>= 1) lsum += __shfl_down_sync(0xffffffffu, lsum, o);
    if ((tid & 31) == 0) red[tid >> 5] = lsum;
    __syncthreads();
    if (tid == 0) {
        float s = 0.f;
#pragma unroll
        for (int i = 0; i < TPB / 32; i++) s += red[i];
        atomicAdd(&g_loss, (double)s);
    }
}

// warp-per-group finalize (proven in round 9)
__global__ void vq_final(float* __restrict__ out, int loss_idx)
{
    __shared__ float pg[N_G];
    int w = threadIdx.x >> 5, lane = threadIdx.x & 31;
    if (w < N_G) {
        float s = 0.f;
        for (int i = lane; i < M_C; i += 32) {
            float p = (float)g_hist[w * M_C + i] / (float)BL;
            s += p * logf(p + 1e-10f);
        }
#pragma unroll
        for (int o = 16; o > 0; o >>= 1) s += __shfl_down_sync(0xffffffffu, s, o);
        if (lane == 0) pg[w] = s;
    }
    __syncthreads();
    if (threadIdx.x == 0) {
        float perp = 0.f;
#pragma unroll
        for (int g = 0; g < N_G; g++) perp += expf(-pg[g]);
        double mean = g_loss / (double)((size_t)N_G * BL * D_C);
        out[loss_idx]     = (float)(0.25 * mean);
        out[loss_idx + 1] = perp;
    }
}

extern "C" void kernel_launch(void* const* d_in, const int* in_sizes, int n_in,
                              void* d_out, int out_size)
{
    const float* x   = (const float*)d_in[0];   // [32, 512, 1024] f32
    const float* emb = (const float*)d_in[1];   // [8, 512, 64]   f32
    float* out = (float*)d_out;

    vq_prep<<<(N_G * NPAIR + 127) / 128, 128>>>(emb);

    dim3 grid(BL / TPB, N_G);
    vq_main<<<grid, TPB>>>(x, emb, out);

    vq_final<<<1, 256>>>(out, out_size - 2);
}